// round 9
// baseline (speedup 1.0000x reference)
#include <cuda_runtime.h>
#include <cuda_bf16.h>
#include <cstdint>
#include <cstddef>

#define NB   4
#define NC   64
#define NL   4096
#define NH   128
#define NKE  192          // [hi|x|x] split-bf16 extended K dimension

#define SCALE_LOG2E 14.4269504088896340737f   // 10 * log2(e)
#define THRESH 1e-3f

// ---------------- device scratch (no allocations allowed) ----------------
__device__ __align__(256) __nv_bfloat16 g_Q[NB*NL*NKE];   // [b][l][192] = [qhi|qlo|qhi]
__device__ __align__(256) __nv_bfloat16 g_K[NB*NL*NKE];   // [b][l][192] = [khi|khi|klo]

// ---------------- projection + leakyrelu + projection + l2norm + bf16 split ----------------
#define PJ_POS 32
#define PJ_GROUPS 2
#define W1_PITCH 68    // [j][c]
#define W2_PITCH 132   // [o][j]
#define XS_PITCH 68    // [p][c]
#define HS_PITCH 132   // [p][j]
#define SA_W1 0
#define SA_W2 (NH*W1_PITCH)                  // 8704
#define SA_XS (SA_W2 + NC*W2_PITCH)          // 17152
#define SA_HS (SA_XS + PJ_POS*XS_PITCH)      // 19328
#define SA_FLOATS (SA_HS + PJ_POS*HS_PITCH)  // 23552
#define SA_BYTES (SA_FLOATS*4)

__global__ void __launch_bounds__(256,2) proj_kernel(const float* __restrict__ xq,
                                                     const float* __restrict__ xk,
                                                     const float* __restrict__ W1,
                                                     const float* __restrict__ W2){
  extern __shared__ float sm_f[];
  float* sm = sm_f;
  const int tid = threadIdx.x;
  const int bpt = NL / (PJ_POS*PJ_GROUPS);     // 64 blocks per (tensor,batch)
  const int tb  = blockIdx.x / bpt;            // 0..7  (0..3 = query, 4..7 = key)
  const int base = (blockIdx.x % bpt) * (PJ_POS*PJ_GROUPS);
  const bool isQ = (tb < NB);
  const int b   = tb & 3;
  const float* __restrict__ src = isQ ? xq : xk;
  __nv_bfloat16* __restrict__ dst = isQ ? g_Q : g_K;

  for (int i = tid; i < NH*NC; i += 256){
    int j = i >> 6, c = i & 63;
    sm[SA_W1 + j*W1_PITCH + c] = W1[i];        // W1[j][c]
  }
  for (int i = tid; i < NC*NH; i += 256){
    int o = i >> 7, j = i & 127;
    sm[SA_W2 + o*W2_PITCH + j] = W2[i];        // W2[o][j]
  }

  const int lanegrp = tid & 31;
  const int pg      = tid >> 5;

  for (int grp = 0; grp < PJ_GROUPS; grp++){
    const int l0 = base + grp*PJ_POS;
    __syncthreads();
    for (int i = tid; i < NC*PJ_POS; i += 256){
      int p = i & 31, c = i >> 5;
      sm[SA_XS + p*XS_PITCH + c] = src[((size_t)b*NC + c)*NL + l0 + p];  // xs[p][c]
    }
    __syncthreads();

    // ---- phase 1: h = leakyrelu(W1 @ x) ----
    {
      float acc[4][4];
      #pragma unroll
      for (int ji=0;ji<4;ji++)
        #pragma unroll
        for (int pi=0;pi<4;pi++) acc[ji][pi]=0.f;
      #pragma unroll 4
      for (int c4 = 0; c4 < NC; c4 += 4){
        float4 w[4], x[4];
        #pragma unroll
        for (int ji=0;ji<4;ji++)
          w[ji] = *(const float4*)&sm[SA_W1 + (lanegrp + ji*32)*W1_PITCH + c4];
        #pragma unroll
        for (int pi=0;pi<4;pi++)
          x[pi] = *(const float4*)&sm[SA_XS + (pg*4+pi)*XS_PITCH + c4];   // broadcast
        #pragma unroll
        for (int pi=0;pi<4;pi++)
          #pragma unroll
          for (int ji=0;ji<4;ji++){
            acc[ji][pi] += w[ji].x*x[pi].x + w[ji].y*x[pi].y
                         + w[ji].z*x[pi].z + w[ji].w*x[pi].w;
          }
      }
      #pragma unroll
      for (int pi=0;pi<4;pi++)
        #pragma unroll
        for (int ji=0;ji<4;ji++){
          float v = acc[ji][pi];
          v = v >= 0.f ? v : 0.01f*v;
          sm[SA_HS + (pg*4+pi)*HS_PITCH + lanegrp + ji*32] = v;   // hs[p][j]
        }
    }
    __syncthreads();

    // ---- phase 2: y = W2 @ h ; normalize ; split to bf16 ----
    {
      float acc[2][4];
      #pragma unroll
      for (int oi=0;oi<2;oi++)
        #pragma unroll
        for (int pi=0;pi<4;pi++) acc[oi][pi]=0.f;
      #pragma unroll 4
      for (int j4 = 0; j4 < NH; j4 += 4){
        float4 w0 = *(const float4*)&sm[SA_W2 + lanegrp*W2_PITCH + j4];
        float4 w1 = *(const float4*)&sm[SA_W2 + (lanegrp+32)*W2_PITCH + j4];
        #pragma unroll
        for (int pi=0;pi<4;pi++){
          float4 h = *(const float4*)&sm[SA_HS + (pg*4+pi)*HS_PITCH + j4]; // broadcast
          acc[0][pi] += w0.x*h.x + w0.y*h.y + w0.z*h.z + w0.w*h.w;
          acc[1][pi] += w1.x*h.x + w1.y*h.y + w1.z*h.z + w1.w*h.w;
        }
      }
      #pragma unroll
      for (int pi=0;pi<4;pi++){
        float ssq = acc[0][pi]*acc[0][pi] + acc[1][pi]*acc[1][pi];
        #pragma unroll
        for (int off=16; off; off>>=1) ssq += __shfl_xor_sync(0xffffffffu, ssq, off);
        float inv = 1.0f / fmaxf(sqrtf(ssq), 1e-12f);
        int p = pg*4 + pi;
        size_t rowbase = ((size_t)b*NL + l0 + p) * NKE;
        #pragma unroll
        for (int oi=0;oi<2;oi++){
          int o = lanegrp + oi*32;
          float v = acc[oi][pi] * inv;
          __nv_bfloat16 hi = __float2bfloat16(v);
          __nv_bfloat16 lo = __float2bfloat16(v - __bfloat162float(hi));
          if (isQ){
            dst[rowbase + o]       = hi;
            dst[rowbase + 64 + o]  = lo;
            dst[rowbase + 128 + o] = hi;
          } else {
            dst[rowbase + o]       = hi;
            dst[rowbase + 64 + o]  = hi;
            dst[rowbase + 128 + o] = lo;
          }
        }
      }
    }
  }
}

// ---------------- attention: 64-row CTAs, 2 CTAs/SM for tail overlap ----------------
#define ATH   128            // 4 warps: 2 row-warps x 2 col-warps (32x32 tiles)
#define CROWS 64             // CTA row-tile
#define CHUNK 64             // K chunk cols
#define NCH   (NL/CHUNK)     // 64 chunks per pass
#define NIT   (2*NCH)        // 128 iterations
#define SROW_B 400           // padded smem row stride (192*2=384 data + 16 pad)
#define TILE_B (CROWS*SROW_B)          // 25600
#define SKB(i) ((i)*TILE_B)            // 3-slot ring; slot 2 holds Q initially
#define SQ_OFF SKB(2)
#define SRS_OFF (3*TILE_B)             // 76800: float rsum[2][64]
#define SINV_OFF (SRS_OFF + 512)
#define SB_TOTAL (SINV_OFF + 256)      // 77568 B -> 2 CTAs/SM

__device__ __forceinline__ float fexp2(float x){
  float y;
  asm("ex2.approx.ftz.f32 %0, %1;" : "=f"(y) : "f"(x));
  return y;
}

__device__ __forceinline__ void cpa16(void* sptr, const void* gptr){
  uint32_t s = (uint32_t)__cvta_generic_to_shared(sptr);
  asm volatile("cp.async.cg.shared.global [%0], [%1], 16;" :: "r"(s), "l"(gptr));
}
__device__ __forceinline__ void cpcommit(){ asm volatile("cp.async.commit_group;"); }
__device__ __forceinline__ void cpwait1(){ asm volatile("cp.async.wait_group 1;"); }

// stage 64 rows of 384B (global, dense) into smem (stride 400B), 128 threads
__device__ __forceinline__ void stage_tile(char* sdst, const __nv_bfloat16* gsrc, int tid){
  const char* gb = (const char*)gsrc;
  #pragma unroll
  for (int i = 0; i < 12; i++){
    int idx = tid + i*ATH;
    int r = idx / 24, o = idx % 24;
    cpa16(sdst + r*SROW_B + o*16, gb + (size_t)r*384 + o*16);
  }
}

__device__ __forceinline__ void ldsm4(uint32_t (&r)[4], uint32_t saddr){
  asm volatile("ldmatrix.sync.aligned.m8n8.x4.shared.b16 {%0,%1,%2,%3}, [%4];"
    : "=r"(r[0]), "=r"(r[1]), "=r"(r[2]), "=r"(r[3]) : "r"(saddr));
}

__device__ __forceinline__ void mma16816(float (&c)[4], const uint32_t (&a)[4],
                                         uint32_t b0, uint32_t b1){
  asm volatile(
    "mma.sync.aligned.m16n8k16.row.col.f32.bf16.bf16.f32 "
    "{%0,%1,%2,%3}, {%4,%5,%6,%7}, {%8,%9}, {%0,%1,%2,%3};"
    : "+f"(c[0]), "+f"(c[1]), "+f"(c[2]), "+f"(c[3])
    : "r"(a[0]), "r"(a[1]), "r"(a[2]), "r"(a[3]), "r"(b0), "r"(b1));
}

__global__ void __launch_bounds__(ATH,2) attn_kernel(float* __restrict__ out){
  extern __shared__ char sm_c[];
  char* sm = sm_c;
  float* rsum = (float*)(sm + SRS_OFF);
  float* invp = (float*)(sm + SINV_OFF);

  const int tid = threadIdx.x;
  const int lane = tid & 31, wid = tid >> 5;
  const int wr = wid >> 1, wc = wid & 1;    // 2 row-warps x 2 col-warps (32x32 tiles)
  const int g = lane >> 2, t = lane & 3;
  const int b = blockIdx.y, rb = blockIdx.x;

  const uint32_t smem_base = (uint32_t)__cvta_generic_to_shared(sm);

  const uint32_t aoff0 = (uint32_t)((wr*32 +  0 + (lane & 15))*SROW_B + ((lane >> 4) & 1)*16);
  const uint32_t aoff1 = (uint32_t)((wr*32 + 16 + (lane & 15))*SROW_B + ((lane >> 4) & 1)*16);
  const uint32_t boff = (uint32_t)((wc*32 + (lane & 7) + ((lane >> 1) & 8))*SROW_B + (lane & 8)*2);

  const __nv_bfloat16* Qg = g_Q + ((size_t)b*NL + (size_t)rb*CROWS)*NKE;
  const __nv_bfloat16* Kg = g_K + (size_t)b*NL*NKE;

  // prologue: {Q(slot2), K0(slot0)} group0, {K1(slot1)} group1
  stage_tile(sm + SQ_OFF, Qg, tid);
  stage_tile(sm + SKB(0), Kg, tid);
  cpcommit();
  stage_tile(sm + SKB(1), Kg + (size_t)CHUNK*NKE, tid);
  cpcommit();

  cpwait1();          // group0 (Q + K0) resident
  __syncthreads();

  // ---- hoist Q (A) fragments: invariant across all 128 iterations ----
  uint32_t afr[12][2][4];
  {
    const uint32_t aA0 = smem_base + SQ_OFF + aoff0;
    const uint32_t aA1 = smem_base + SQ_OFF + aoff1;
    #pragma unroll
    for (int ks = 0; ks < 12; ks++){
      ldsm4(afr[ks][0], aA0 + ks*32);
      ldsm4(afr[ks][1], aA1 + ks*32);
    }
  }
  __syncthreads();    // all warps done reading Q before slot2 is re-staged

  float esum[2][2] = {{0.f,0.f},{0.f,0.f}};
  float vinv[2][2] = {{0.f,0.f},{0.f,0.f}};

  for (int it = 0; it < NIT; it++){
    if (it > 0){
      cpwait1();               // K[it] resident (committed 2 iterations ago)
      __syncthreads();         // fences buffer reuse (readers of slot (it+2)%3 done)
    }
    {
      int nx = it + 2;
      if (nx < NIT) stage_tile(sm + SKB(nx % 3), Kg + (size_t)(nx & (NCH-1))*CHUNK*NKE, tid);
      cpcommit();              // uniform group accounting (may be empty)
    }

    const uint32_t bB = smem_base + SKB(it % 3) + boff;

    float acc[2][4][4];
    #pragma unroll
    for (int mt=0;mt<2;mt++)
      #pragma unroll
      for (int nt=0;nt<4;nt++)
        #pragma unroll
        for (int i=0;i<4;i++) acc[mt][nt][i]=0.f;

    #pragma unroll
    for (int ks = 0; ks < 12; ks++){
      #pragma unroll
      for (int ntp = 0; ntp < 2; ntp++){
        uint32_t br[4];
        ldsm4(br, bB + ntp*16*SROW_B + ks*32);
        mma16816(acc[0][2*ntp],   afr[ks][0], br[0], br[1]);
        mma16816(acc[1][2*ntp],   afr[ks][1], br[0], br[1]);
        mma16816(acc[0][2*ntp+1], afr[ks][0], br[2], br[3]);
        mma16816(acc[1][2*ntp+1], afr[ks][1], br[2], br[3]);
      }
    }

    if (it < NCH){
      // pass 0 epilogue: accumulate exp-sums
      #pragma unroll
      for (int mt=0;mt<2;mt++)
        #pragma unroll
        for (int nt=0;nt<4;nt++){
          esum[mt][0] += fexp2(acc[mt][nt][0]*SCALE_LOG2E) + fexp2(acc[mt][nt][1]*SCALE_LOG2E);
          esum[mt][1] += fexp2(acc[mt][nt][2]*SCALE_LOG2E) + fexp2(acc[mt][nt][3]*SCALE_LOG2E);
        }
    } else {
      // pass 1 epilogue: normalize + threshold + store
      int ci = it - NCH;
      #pragma unroll
      for (int mt=0;mt<2;mt++){
        int r0 = rb*CROWS + wr*32 + mt*16 + g;
        float* o0 = out + ((size_t)b*NL + r0)*NL + ci*CHUNK + wc*32 + t*2;
        float* o1 = o0 + (size_t)8*NL;
        #pragma unroll
        for (int nt=0;nt<4;nt++){
          float w00 = fexp2(acc[mt][nt][0]*SCALE_LOG2E)*vinv[mt][0];
          float w01 = fexp2(acc[mt][nt][1]*SCALE_LOG2E)*vinv[mt][0];
          float w10 = fexp2(acc[mt][nt][2]*SCALE_LOG2E)*vinv[mt][1];
          float w11 = fexp2(acc[mt][nt][3]*SCALE_LOG2E)*vinv[mt][1];
          float2 v0 = make_float2(w00 > THRESH ? w00 : 0.f, w01 > THRESH ? w01 : 0.f);
          float2 v1 = make_float2(w10 > THRESH ? w10 : 0.f, w11 > THRESH ? w11 : 0.f);
          *(float2*)(o0 + nt*8) = v0;
          *(float2*)(o1 + nt*8) = v1;
        }
      }
    }

    if (it == NCH-1){
      // pass-0 complete: quad-reduce, publish per-wc partials, combine halves
      #pragma unroll
      for (int mt=0;mt<2;mt++)
        #pragma unroll
        for (int hh=0;hh<2;hh++){
          float v = esum[mt][hh];
          v += __shfl_xor_sync(0xffffffffu, v, 1);
          v += __shfl_xor_sync(0xffffffffu, v, 2);
          esum[mt][hh] = v;
        }
      if (t == 0){
        #pragma unroll
        for (int mt=0;mt<2;mt++){
          rsum[wc*64 + wr*32 + mt*16 + g]     = esum[mt][0];
          rsum[wc*64 + wr*32 + mt*16 + g + 8] = esum[mt][1];
        }
      }
      __syncthreads();
      if (tid < 64) invp[tid] = 1.0f / (rsum[tid] + rsum[64 + tid]);
      __syncthreads();
      #pragma unroll
      for (int mt=0;mt<2;mt++){
        vinv[mt][0] = invp[wr*32 + mt*16 + g];
        vinv[mt][1] = invp[wr*32 + mt*16 + g + 8];
      }
    }
  }
}

// ---------------- launch ----------------
extern "C" void kernel_launch(void* const* d_in, const int* in_sizes, int n_in,
                              void* d_out, int out_size){
  const float* q  = (const float*)d_in[0];
  const float* k  = (const float*)d_in[1];
  const float* W1 = (const float*)d_in[2];
  const float* W2 = (const float*)d_in[3];
  float* out = (float*)d_out;

  cudaFuncSetAttribute(proj_kernel, cudaFuncAttributeMaxDynamicSharedMemorySize, SA_BYTES);
  cudaFuncSetAttribute(attn_kernel, cudaFuncAttributeMaxDynamicSharedMemorySize, SB_TOTAL);

  proj_kernel<<<2*NB*NL/(PJ_POS*PJ_GROUPS), 256, SA_BYTES>>>(q, k, W1, W2);
  attn_kernel<<<dim3(NL/CROWS, NB), ATH, SB_TOTAL>>>(out);
}

// round 10
// speedup vs baseline: 1.1275x; 1.1275x over previous
#include <cuda_runtime.h>
#include <cuda_bf16.h>
#include <cstdint>
#include <cstddef>

#define NB   4
#define NC   64
#define NL   4096
#define NH   128
#define NKE  192          // [hi|x|x] split-bf16 extended K dimension

#define SCALE_LOG2E 14.4269504088896340737f   // 10 * log2(e)
#define THRESH 1e-3f

// ---------------- device scratch (no allocations allowed) ----------------
__device__ __align__(256) __nv_bfloat16 g_Q[NB*NL*NKE];   // [b][l][192] = [qhi|qlo|qhi]
__device__ __align__(256) __nv_bfloat16 g_K[NB*NL*NKE];   // [b][l][192] = [khi|khi|klo]

// ---------------- projection + leakyrelu + projection + l2norm + bf16 split ----------------
#define PJ_POS 32
#define PJ_GROUPS 2
#define W1_PITCH 68    // [j][c]
#define W2_PITCH 132   // [o][j]
#define XS_PITCH 68    // [p][c]
#define HS_PITCH 132   // [p][j]
#define SA_W1 0
#define SA_W2 (NH*W1_PITCH)                  // 8704
#define SA_XS (SA_W2 + NC*W2_PITCH)          // 17152
#define SA_HS (SA_XS + PJ_POS*XS_PITCH)      // 19328
#define SA_FLOATS (SA_HS + PJ_POS*HS_PITCH)  // 23552
#define SA_BYTES (SA_FLOATS*4)

__global__ void __launch_bounds__(256,2) proj_kernel(const float* __restrict__ xq,
                                                     const float* __restrict__ xk,
                                                     const float* __restrict__ W1,
                                                     const float* __restrict__ W2){
  extern __shared__ float sm_f[];
  float* sm = sm_f;
  const int tid = threadIdx.x;
  const int bpt = NL / (PJ_POS*PJ_GROUPS);     // 64 blocks per (tensor,batch)
  const int tb  = blockIdx.x / bpt;            // 0..7  (0..3 = query, 4..7 = key)
  const int base = (blockIdx.x % bpt) * (PJ_POS*PJ_GROUPS);
  const bool isQ = (tb < NB);
  const int b   = tb & 3;
  const float* __restrict__ src = isQ ? xq : xk;
  __nv_bfloat16* __restrict__ dst = isQ ? g_Q : g_K;

  for (int i = tid; i < NH*NC; i += 256){
    int j = i >> 6, c = i & 63;
    sm[SA_W1 + j*W1_PITCH + c] = W1[i];        // W1[j][c]
  }
  for (int i = tid; i < NC*NH; i += 256){
    int o = i >> 7, j = i & 127;
    sm[SA_W2 + o*W2_PITCH + j] = W2[i];        // W2[o][j]
  }

  const int lanegrp = tid & 31;
  const int pg      = tid >> 5;

  for (int grp = 0; grp < PJ_GROUPS; grp++){
    const int l0 = base + grp*PJ_POS;
    __syncthreads();
    for (int i = tid; i < NC*PJ_POS; i += 256){
      int p = i & 31, c = i >> 5;
      sm[SA_XS + p*XS_PITCH + c] = src[((size_t)b*NC + c)*NL + l0 + p];  // xs[p][c]
    }
    __syncthreads();

    // ---- phase 1: h = leakyrelu(W1 @ x) ----
    {
      float acc[4][4];
      #pragma unroll
      for (int ji=0;ji<4;ji++)
        #pragma unroll
        for (int pi=0;pi<4;pi++) acc[ji][pi]=0.f;
      #pragma unroll 4
      for (int c4 = 0; c4 < NC; c4 += 4){
        float4 w[4], x[4];
        #pragma unroll
        for (int ji=0;ji<4;ji++)
          w[ji] = *(const float4*)&sm[SA_W1 + (lanegrp + ji*32)*W1_PITCH + c4];
        #pragma unroll
        for (int pi=0;pi<4;pi++)
          x[pi] = *(const float4*)&sm[SA_XS + (pg*4+pi)*XS_PITCH + c4];   // broadcast
        #pragma unroll
        for (int pi=0;pi<4;pi++)
          #pragma unroll
          for (int ji=0;ji<4;ji++){
            acc[ji][pi] += w[ji].x*x[pi].x + w[ji].y*x[pi].y
                         + w[ji].z*x[pi].z + w[ji].w*x[pi].w;
          }
      }
      #pragma unroll
      for (int pi=0;pi<4;pi++)
        #pragma unroll
        for (int ji=0;ji<4;ji++){
          float v = acc[ji][pi];
          v = v >= 0.f ? v : 0.01f*v;
          sm[SA_HS + (pg*4+pi)*HS_PITCH + lanegrp + ji*32] = v;   // hs[p][j]
        }
    }
    __syncthreads();

    // ---- phase 2: y = W2 @ h ; normalize ; split to bf16 ----
    {
      float acc[2][4];
      #pragma unroll
      for (int oi=0;oi<2;oi++)
        #pragma unroll
        for (int pi=0;pi<4;pi++) acc[oi][pi]=0.f;
      #pragma unroll 4
      for (int j4 = 0; j4 < NH; j4 += 4){
        float4 w0 = *(const float4*)&sm[SA_W2 + lanegrp*W2_PITCH + j4];
        float4 w1 = *(const float4*)&sm[SA_W2 + (lanegrp+32)*W2_PITCH + j4];
        #pragma unroll
        for (int pi=0;pi<4;pi++){
          float4 h = *(const float4*)&sm[SA_HS + (pg*4+pi)*HS_PITCH + j4]; // broadcast
          acc[0][pi] += w0.x*h.x + w0.y*h.y + w0.z*h.z + w0.w*h.w;
          acc[1][pi] += w1.x*h.x + w1.y*h.y + w1.z*h.z + w1.w*h.w;
        }
      }
      #pragma unroll
      for (int pi=0;pi<4;pi++){
        float ssq = acc[0][pi]*acc[0][pi] + acc[1][pi]*acc[1][pi];
        #pragma unroll
        for (int off=16; off; off>>=1) ssq += __shfl_xor_sync(0xffffffffu, ssq, off);
        float inv = 1.0f / fmaxf(sqrtf(ssq), 1e-12f);
        int p = pg*4 + pi;
        size_t rowbase = ((size_t)b*NL + l0 + p) * NKE;
        #pragma unroll
        for (int oi=0;oi<2;oi++){
          int o = lanegrp + oi*32;
          float v = acc[oi][pi] * inv;
          __nv_bfloat16 hi = __float2bfloat16(v);
          __nv_bfloat16 lo = __float2bfloat16(v - __bfloat162float(hi));
          if (isQ){
            dst[rowbase + o]       = hi;
            dst[rowbase + 64 + o]  = lo;
            dst[rowbase + 128 + o] = hi;
          } else {
            dst[rowbase + o]       = hi;
            dst[rowbase + 64 + o]  = hi;
            dst[rowbase + 128 + o] = lo;
          }
        }
      }
    }
  }
}

// ----- attention: two independent warp-groups pipelined over odd/even chunks -----
#define ATH   256            // 8 warps: 2 groups x 4 row-warps
#define CHUNK 64             // key-cols per chunk
#define NCHG  32             // chunks per group per pass (64 total / 2 groups)
#define NJ    64             // iterations per group (2 passes x 32)
#define SROW_B 400           // padded smem row stride (192*2=384 data + 16 pad)
#define QTILE_B (128*SROW_B)           // 51200
#define KTILE_B (CHUNK*SROW_B)         // 25600
#define SQ_OFF  0
#define SKB(gr,s) (QTILE_B + ((gr)*3+(s))*KTILE_B)
#define SRS_OFF (QTILE_B + 6*KTILE_B)  // 204800: float rsum[2][128]
#define SINV_OFF (SRS_OFF + 1024)
#define SB_TOTAL (SINV_OFF + 512)      // 206336 B

__device__ __forceinline__ float fexp2(float x){
  float y;
  asm("ex2.approx.ftz.f32 %0, %1;" : "=f"(y) : "f"(x));
  return y;
}
__device__ __forceinline__ void cpa16(void* sptr, const void* gptr){
  uint32_t s = (uint32_t)__cvta_generic_to_shared(sptr);
  asm volatile("cp.async.cg.shared.global [%0], [%1], 16;" :: "r"(s), "l"(gptr));
}
__device__ __forceinline__ void cpcommit(){ asm volatile("cp.async.commit_group;"); }
__device__ __forceinline__ void cpwait1(){ asm volatile("cp.async.wait_group 1;"); }
__device__ __forceinline__ void groupbar(int id){
  asm volatile("bar.sync %0, 128;" :: "r"(id) : "memory");
}

// stage 128 Q rows with 256 threads
__device__ __forceinline__ void stage_q(char* sdst, const __nv_bfloat16* gsrc, int tid){
  const char* gb = (const char*)gsrc;
  #pragma unroll
  for (int i = 0; i < 12; i++){
    int idx = tid + i*256;
    int r = idx / 24, o = idx % 24;
    cpa16(sdst + r*SROW_B + o*16, gb + (size_t)r*384 + o*16);
  }
}
// stage 64 key rows with this group's 128 threads
__device__ __forceinline__ void stage_k(char* sdst, const __nv_bfloat16* gsrc, int gtid){
  const char* gb = (const char*)gsrc;
  #pragma unroll
  for (int i = 0; i < 12; i++){
    int idx = gtid + i*128;
    int r = idx / 24, o = idx % 24;
    cpa16(sdst + r*SROW_B + o*16, gb + (size_t)r*384 + o*16);
  }
}

__device__ __forceinline__ void ldsm4(uint32_t (&r)[4], uint32_t saddr){
  asm volatile("ldmatrix.sync.aligned.m8n8.x4.shared.b16 {%0,%1,%2,%3}, [%4];"
    : "=r"(r[0]), "=r"(r[1]), "=r"(r[2]), "=r"(r[3]) : "r"(saddr));
}
__device__ __forceinline__ void mma16816(float (&c)[4], const uint32_t (&a)[4],
                                         uint32_t b0, uint32_t b1){
  asm volatile(
    "mma.sync.aligned.m16n8k16.row.col.f32.bf16.bf16.f32 "
    "{%0,%1,%2,%3}, {%4,%5,%6,%7}, {%8,%9}, {%0,%1,%2,%3};"
    : "+f"(c[0]), "+f"(c[1]), "+f"(c[2]), "+f"(c[3])
    : "r"(a[0]), "r"(a[1]), "r"(a[2]), "r"(a[3]), "r"(b0), "r"(b1));
}

__global__ void __launch_bounds__(ATH,1) attn_kernel(float* __restrict__ out){
  extern __shared__ char sm_c[];
  char* sm = sm_c;
  float* rsum = (float*)(sm + SRS_OFF);
  float* invp = (float*)(sm + SINV_OFF);

  const int tid = threadIdx.x;
  const int lane = tid & 31, wid = tid >> 5;
  const int gidx = wid >> 2;        // warp-group 0/1 (even/odd chunks)
  const int gtid = tid & 127;
  const int wr = wid & 3;           // row-warp within group: rows wr*32..wr*32+31
  const int g = lane >> 2, t = lane & 3;
  const int barid = 1 + gidx;
  const int b = blockIdx.y, rb = blockIdx.x;

  const uint32_t smem_base = (uint32_t)__cvta_generic_to_shared(sm);

  const uint32_t aoff0 = (uint32_t)((wr*32 +  0 + (lane & 15))*SROW_B + ((lane >> 4) & 1)*16);
  const uint32_t aoff1 = (uint32_t)((wr*32 + 16 + (lane & 15))*SROW_B + ((lane >> 4) & 1)*16);
  const uint32_t boff = (uint32_t)(((lane & 7) + ((lane >> 1) & 8))*SROW_B + (lane & 8)*2);

  const __nv_bfloat16* Qg = g_Q + ((size_t)b*NL + (size_t)rb*128)*NKE;
  const __nv_bfloat16* Kg = g_K + (size_t)b*NL*NKE;

  // group-local chunk sequence: L(j) = gidx + 2*(j mod 32)
  // prologue: {Q + L(0)} group0, {L(1)} group1 (per-thread cp.async accounting)
  stage_q(sm + SQ_OFF, Qg, tid);
  stage_k(sm + SKB(gidx,0), Kg + (size_t)(gidx)*CHUNK*NKE, gtid);
  cpcommit();
  stage_k(sm + SKB(gidx,1), Kg + (size_t)(gidx+2)*CHUNK*NKE, gtid);
  cpcommit();
  cpwait1();          // this thread's Q part + L(0) done
  __syncthreads();    // everyone's Q parts visible

  // ---- hoist Q (A) fragments: invariant; Q region never reused ----
  uint32_t afr[12][2][4];
  {
    const uint32_t aA0 = smem_base + SQ_OFF + aoff0;
    const uint32_t aA1 = smem_base + SQ_OFF + aoff1;
    #pragma unroll
    for (int ks = 0; ks < 12; ks++){
      ldsm4(afr[ks][0], aA0 + ks*32);
      ldsm4(afr[ks][1], aA1 + ks*32);
    }
  }

  float esum[2][2] = {{0.f,0.f},{0.f,0.f}};
  float vinv[2][2] = {{0.f,0.f},{0.f,0.f}};

  for (int j = 0; j < NJ; j++){
    if (j > 0){
      cpwait1();             // L(j) resident for this thread
      groupbar(barid);       // group-only: slot (j+2)%3 readers are done
    }
    {
      int nx = j + 2;
      if (nx < NJ){
        int cg = gidx + 2*(nx & (NCHG-1));
        stage_k(sm + SKB(gidx, nx % 3), Kg + (size_t)cg*CHUNK*NKE, gtid);
      }
      cpcommit();            // uniform per-thread group accounting
    }

    const uint32_t bB = smem_base + SKB(gidx, j % 3) + boff;

    float acc[2][8][4];
    #pragma unroll
    for (int mt=0;mt<2;mt++)
      #pragma unroll
      for (int nt=0;nt<8;nt++)
        #pragma unroll
        for (int i=0;i<4;i++) acc[mt][nt][i]=0.f;

    #pragma unroll
    for (int ks = 0; ks < 12; ks++){
      #pragma unroll
      for (int ntp = 0; ntp < 4; ntp++){
        uint32_t br[4];
        ldsm4(br, bB + ntp*16*SROW_B + ks*32);
        mma16816(acc[0][2*ntp],   afr[ks][0], br[0], br[1]);
        mma16816(acc[1][2*ntp],   afr[ks][1], br[0], br[1]);
        mma16816(acc[0][2*ntp+1], afr[ks][0], br[2], br[3]);
        mma16816(acc[1][2*ntp+1], afr[ks][1], br[2], br[3]);
      }
    }

    if (j < NCHG){
      // pass 0 epilogue: accumulate exp-sums
      #pragma unroll
      for (int mt=0;mt<2;mt++)
        #pragma unroll
        for (int nt=0;nt<8;nt++){
          esum[mt][0] += fexp2(acc[mt][nt][0]*SCALE_LOG2E) + fexp2(acc[mt][nt][1]*SCALE_LOG2E);
          esum[mt][1] += fexp2(acc[mt][nt][2]*SCALE_LOG2E) + fexp2(acc[mt][nt][3]*SCALE_LOG2E);
        }
    } else {
      // pass 1 epilogue: normalize + threshold + store (this group's chunk cols)
      int cg = gidx + 2*(j & (NCHG-1));
      #pragma unroll
      for (int mt=0;mt<2;mt++){
        int r0 = rb*128 + wr*32 + mt*16 + g;
        float* o0 = out + ((size_t)b*NL + r0)*NL + cg*CHUNK + t*2;
        float* o1 = o0 + (size_t)8*NL;
        #pragma unroll
        for (int nt=0;nt<8;nt++){
          float w00 = fexp2(acc[mt][nt][0]*SCALE_LOG2E)*vinv[mt][0];
          float w01 = fexp2(acc[mt][nt][1]*SCALE_LOG2E)*vinv[mt][0];
          float w10 = fexp2(acc[mt][nt][2]*SCALE_LOG2E)*vinv[mt][1];
          float w11 = fexp2(acc[mt][nt][3]*SCALE_LOG2E)*vinv[mt][1];
          float2 v0 = make_float2(w00 > THRESH ? w00 : 0.f, w01 > THRESH ? w01 : 0.f);
          float2 v1 = make_float2(w10 > THRESH ? w10 : 0.f, w11 > THRESH ? w11 : 0.f);
          *(float2*)(o0 + nt*8) = v0;
          *(float2*)(o1 + nt*8) = v1;
        }
      }
    }

    if (j == NCHG-1){
      // pass-0 complete: quad-reduce rows, publish per-group partials, combine
      #pragma unroll
      for (int mt=0;mt<2;mt++)
        #pragma unroll
        for (int hh=0;hh<2;hh++){
          float v = esum[mt][hh];
          v += __shfl_xor_sync(0xffffffffu, v, 1);
          v += __shfl_xor_sync(0xffffffffu, v, 2);
          esum[mt][hh] = v;
        }
      if (t == 0){
        #pragma unroll
        for (int mt=0;mt<2;mt++){
          rsum[gidx*128 + wr*32 + mt*16 + g]     = esum[mt][0];
          rsum[gidx*128 + wr*32 + mt*16 + g + 8] = esum[mt][1];
        }
      }
      __syncthreads();        // both groups rendezvous once
      if (tid < 128) invp[tid] = 1.0f / (rsum[tid] + rsum[128 + tid]);
      __syncthreads();
      #pragma unroll
      for (int mt=0;mt<2;mt++){
        vinv[mt][0] = invp[wr*32 + mt*16 + g];
        vinv[mt][1] = invp[wr*32 + mt*16 + g + 8];
      }
    }
  }
}

// ---------------- launch ----------------
extern "C" void kernel_launch(void* const* d_in, const int* in_sizes, int n_in,
                              void* d_out, int out_size){
  const float* q  = (const float*)d_in[0];
  const float* k  = (const float*)d_in[1];
  const float* W1 = (const float*)d_in[2];
  const float* W2 = (const float*)d_in[3];
  float* out = (float*)d_out;

  cudaFuncSetAttribute(proj_kernel, cudaFuncAttributeMaxDynamicSharedMemorySize, SA_BYTES);
  cudaFuncSetAttribute(attn_kernel, cudaFuncAttributeMaxDynamicSharedMemorySize, SB_TOTAL);

  proj_kernel<<<2*NB*NL/(PJ_POS*PJ_GROUPS), 256, SA_BYTES>>>(q, k, W1, W2);
  attn_kernel<<<dim3(NL/128, NB), ATH, SB_TOTAL>>>(out);
}